// round 2
// baseline (speedup 1.0000x reference)
#include <cuda_runtime.h>
#include <cuda_bf16.h>

#define NN 100000
#define EE 1600000

// Scratch (device globals: allocation-free rule).
__device__ float g_bufA[NN * 64];     // aggregation output / GEMM input
__device__ float g_bufB[NN * 64];     // GEMM output (hidden layers)
__device__ int   g_offs[NN + 1];      // CSR row offsets (by dst)
__device__ int   g_cursor[NN];        // scatter cursors
__device__ uint2 g_perm[EE];          // {src, weight_bits} sorted by dst

// ---------------------------------------------------------------------------
// CSR build
// ---------------------------------------------------------------------------
__global__ void k_zero_offs(int n1) {
    int i = blockIdx.x * blockDim.x + threadIdx.x;
    if (i < n1) g_offs[i] = 0;
}

__global__ void k_hist(const int* __restrict__ dst, int e) {
    int i = blockIdx.x * blockDim.x + threadIdx.x;
    if (i < e) atomicAdd(&g_offs[dst[i] + 1], 1);
}

// Single-block inclusive prefix scan over g_offs[0..len). Also seeds cursors.
__global__ void k_scan(int len, int nnodes) {
    __shared__ int s[1024];
    int t = threadIdx.x;
    int chunk = (len + 1023) / 1024;
    int b0 = t * chunk;
    int b1 = min(b0 + chunk, len);
    int sum = 0;
    for (int i = b0; i < b1; i++) sum += g_offs[i];
    s[t] = sum;
    __syncthreads();
    for (int off = 1; off < 1024; off <<= 1) {
        int v = (t >= off) ? s[t - off] : 0;
        __syncthreads();
        s[t] += v;
        __syncthreads();
    }
    int run = s[t] - sum;   // exclusive base for this chunk
    for (int i = b0; i < b1; i++) {
        run += g_offs[i];
        g_offs[i] = run;                    // inclusive prefix
        if (i < nnodes) g_cursor[i] = run;  // node i's start offset
    }
}

__global__ void k_scatter(const int* __restrict__ src, const int* __restrict__ dst,
                          const float* __restrict__ w, int e) {
    int i = blockIdx.x * blockDim.x + threadIdx.x;
    if (i < e) {
        int p = atomicAdd(&g_cursor[dst[i]], 1);
        g_perm[p] = make_uint2((unsigned)src[i], __float_as_uint(w[i]));
    }
}

// ---------------------------------------------------------------------------
// Aggregation: g_bufA[n] = sum_{e: dst(e)==n} w_e * H[src(e)]   (64 channels)
// One warp per node; lane handles a float2 channel pair. Pure gather, no
// atomics; H + perm fit in L2 so this is L2-throughput bound.
// ---------------------------------------------------------------------------
__device__ __forceinline__ void aggregate_body(const float2* __restrict__ H, int n) {
    int gw   = (blockIdx.x * blockDim.x + threadIdx.x) >> 5;
    int lane = threadIdx.x & 31;
    if (gw >= n) return;
    int beg = g_offs[gw];
    int end = g_offs[gw + 1];
    float2 acc = make_float2(0.f, 0.f);
    int e = beg;
    // unroll-4 for memory-level parallelism (L2 hit latency ~250 cyc)
    for (; e + 4 <= end; e += 4) {
        uint2 p0 = g_perm[e + 0];
        uint2 p1 = g_perm[e + 1];
        uint2 p2 = g_perm[e + 2];
        uint2 p3 = g_perm[e + 3];
        float2 v0 = H[p0.x * 32u + lane];
        float2 v1 = H[p1.x * 32u + lane];
        float2 v2 = H[p2.x * 32u + lane];
        float2 v3 = H[p3.x * 32u + lane];
        float w0 = __uint_as_float(p0.y);
        float w1 = __uint_as_float(p1.y);
        float w2 = __uint_as_float(p2.y);
        float w3 = __uint_as_float(p3.y);
        acc.x = fmaf(w0, v0.x, acc.x); acc.y = fmaf(w0, v0.y, acc.y);
        acc.x = fmaf(w1, v1.x, acc.x); acc.y = fmaf(w1, v1.y, acc.y);
        acc.x = fmaf(w2, v2.x, acc.x); acc.y = fmaf(w2, v2.y, acc.y);
        acc.x = fmaf(w3, v3.x, acc.x); acc.y = fmaf(w3, v3.y, acc.y);
    }
    for (; e < end; ++e) {
        uint2 p = g_perm[e];
        float2 v = H[p.x * 32u + lane];
        float w = __uint_as_float(p.y);
        acc.x = fmaf(w, v.x, acc.x);
        acc.y = fmaf(w, v.y, acc.y);
    }
    ((float2*)g_bufA)[gw * 32 + lane] = acc;
}

// Input = external pointer (layer 0: x)
__global__ void k_aggregate_ext(const float2* __restrict__ H, int n) {
    aggregate_body(H, n);
}
// Input = g_bufB (layers 1..4)
__global__ void k_aggregate_fromB(int n) {
    aggregate_body((const float2*)g_bufB, n);
}

// ---------------------------------------------------------------------------
// GEMM: Y[n, outc] = relu?(g_bufA[n,64] @ W[64,outc] + b[outc])
// Block: 256 threads, 64 rows. Thread = (row = tid>>2, colgroup = tid&3),
// computes 16 cols. W in smem (zero-padded to 64 cols), float4 LDS reads.
// ---------------------------------------------------------------------------
__device__ __forceinline__ void gemm_body(const float* __restrict__ Wg,
                                          const float* __restrict__ bg,
                                          float* __restrict__ Y,
                                          int n, int outc, int relu) {
    __shared__ float Ws[64 * 64];
    __shared__ float bs[64];
    int tid = threadIdx.x;
    for (int i = tid; i < 64 * 64; i += 256) Ws[i] = 0.f;
    __syncthreads();
    for (int i = tid; i < 64 * outc; i += 256) {
        int k = i / outc, c = i % outc;
        Ws[k * 64 + c] = Wg[i];
    }
    if (tid < 64) bs[tid] = (tid < outc) ? bg[tid] : 0.f;
    __syncthreads();

    int row = blockIdx.x * 64 + (tid >> 2);
    int cg  = tid & 3;
    float acc[16];
#pragma unroll
    for (int j = 0; j < 16; j++) acc[j] = 0.f;

    if (row < n) {
        const float4* Xr = (const float4*)(g_bufA + (size_t)row * 64);
#pragma unroll
        for (int kc = 0; kc < 16; kc++) {
            float4 xv = Xr[kc];
#pragma unroll
            for (int k2 = 0; k2 < 4; k2++) {
                float xs = (k2 == 0) ? xv.x : (k2 == 1) ? xv.y : (k2 == 2) ? xv.z : xv.w;
                const float4* wrow = (const float4*)(&Ws[(kc * 4 + k2) * 64 + cg * 16]);
#pragma unroll
                for (int jj = 0; jj < 4; jj++) {
                    float4 w4 = wrow[jj];
                    acc[jj * 4 + 0] = fmaf(xs, w4.x, acc[jj * 4 + 0]);
                    acc[jj * 4 + 1] = fmaf(xs, w4.y, acc[jj * 4 + 1]);
                    acc[jj * 4 + 2] = fmaf(xs, w4.z, acc[jj * 4 + 2]);
                    acc[jj * 4 + 3] = fmaf(xs, w4.w, acc[jj * 4 + 3]);
                }
            }
        }
#pragma unroll
        for (int j = 0; j < 16; j++) {
            int c = cg * 16 + j;
            float v = acc[j] + bs[c];
            if (relu) v = fmaxf(v, 0.f);
            if (c < outc) Y[(size_t)row * outc + c] = v;
        }
    }
}

// Hidden layers: write g_bufB, outc=64, relu.
__global__ void k_gemm_toB(const float* __restrict__ Wg, const float* __restrict__ bg,
                           int n) {
    gemm_body(Wg, bg, g_bufB, n, 64, 1);
}
// Output layer: write external d_out, outc=40, no relu.
__global__ void k_gemm_out(const float* __restrict__ Wg, const float* __restrict__ bg,
                           float* __restrict__ Y, int n, int outc) {
    gemm_body(Wg, bg, Y, n, outc, 0);
}

// ---------------------------------------------------------------------------
// Launch
// inputs: x[N,64], edge_weight[E], W[4,64,64], b[4,64], W_out[64,40],
//         b_out[40], edge_src[E], edge_dst[E]  -> out[N,40] f32
// ---------------------------------------------------------------------------
extern "C" void kernel_launch(void* const* d_in, const int* in_sizes, int n_in,
                              void* d_out, int out_size) {
    const float* x    = (const float*)d_in[0];
    const float* ew   = (const float*)d_in[1];
    const float* W    = (const float*)d_in[2];
    const float* b    = (const float*)d_in[3];
    const float* Wout = (const float*)d_in[4];
    const float* bout = (const float*)d_in[5];
    const int*   esrc = (const int*)d_in[6];
    const int*   edst = (const int*)d_in[7];

    int n = in_sizes[0] / 64;   // 100000
    int e = in_sizes[6];        // 1600000

    // --- CSR build (dst-sorted) ---
    k_zero_offs<<<(n + 256) / 256, 256>>>(n + 1);
    k_hist<<<(e + 255) / 256, 256>>>(edst, e);
    k_scan<<<1, 1024>>>(n + 1, n);
    k_scatter<<<(e + 255) / 256, 256>>>(esrc, edst, ew, e);

    int aggBlocks  = (n * 32 + 255) / 256;
    int gemmBlocks = (n + 63) / 64;

    // layer 0: agg(x) -> A ; gemm A,W0 -> B (relu)
    k_aggregate_ext<<<aggBlocks, 256>>>((const float2*)x, n);
    k_gemm_toB<<<gemmBlocks, 256>>>(W, b, n);
    // layers 1..3
    for (int l = 1; l < 4; ++l) {
        k_aggregate_fromB<<<aggBlocks, 256>>>(n);
        k_gemm_toB<<<gemmBlocks, 256>>>(W + (size_t)l * 64 * 64, b + (size_t)l * 64, n);
    }
    // final layer: agg -> A ; gemm A,W_out -> d_out (no relu, outc=40)
    k_aggregate_fromB<<<aggBlocks, 256>>>(n);
    k_gemm_out<<<gemmBlocks, 256>>>(Wout, bout, (float*)d_out, n, 40);
}

// round 7
// speedup vs baseline: 1.3073x; 1.3073x over previous
#include <cuda_runtime.h>
#include <cuda_bf16.h>

#define NN 100000
#define EE 1600000

// Scratch (device globals: allocation-free rule).
__device__ float g_bufA[NN * 64];
__device__ float g_bufB[NN * 64];
__device__ int   g_offs[NN + 1];      // CSR row offsets (by dst)
__device__ int   g_cursor[NN];        // scatter cursors
__device__ uint2 g_perm[EE];          // {src, weight_bits} sorted by dst

// ---------------------------------------------------------------------------
// CSR build
// ---------------------------------------------------------------------------
__global__ void k_zero_offs(int n1) {
    int i = blockIdx.x * blockDim.x + threadIdx.x;
    if (i < n1) g_offs[i] = 0;
}

__global__ void k_hist(const int* __restrict__ dst, int e) {
    int i = blockIdx.x * blockDim.x + threadIdx.x;
    if (i < e) atomicAdd(&g_offs[dst[i] + 1], 1);
}

// Single-block inclusive prefix scan over g_offs[0..len). Also seeds cursors.
__global__ void k_scan(int len, int nnodes) {
    __shared__ int s[1024];
    int t = threadIdx.x;
    int chunk = (len + 1023) / 1024;
    int b0 = t * chunk;
    int b1 = min(b0 + chunk, len);
    int sum = 0;
    for (int i = b0; i < b1; i++) sum += g_offs[i];
    s[t] = sum;
    __syncthreads();
    for (int off = 1; off < 1024; off <<= 1) {
        int v = (t >= off) ? s[t - off] : 0;
        __syncthreads();
        s[t] += v;
        __syncthreads();
    }
    int run = s[t] - sum;   // exclusive base for this chunk
    for (int i = b0; i < b1; i++) {
        run += g_offs[i];
        g_offs[i] = run;
        if (i < nnodes) g_cursor[i] = run;
    }
}

__global__ void k_scatter(const int* __restrict__ src, const int* __restrict__ dst,
                          const float* __restrict__ w, int e) {
    int i = blockIdx.x * blockDim.x + threadIdx.x;
    if (i < e) {
        int p = atomicAdd(&g_cursor[dst[i]], 1);
        g_perm[p] = make_uint2((unsigned)src[i], __float_as_uint(w[i]));
    }
}

// ---------------------------------------------------------------------------
// Fused GCN layer: Hout[n] = act( (sum_e w_e * Hin[src_e]) @ W + b )
// One warp per node, grid-stride. Aggregated row lives across the warp
// (float2/lane = 64 ch). Mini-GEMM via warp shuffles + W in smem.
// W is loaded to smem ONCE per block (zero-padded to 64x64).
// ---------------------------------------------------------------------------
#define LAYER_BLOCKS 888   // 148 SMs * 6 blocks

__device__ __forceinline__ void layer_body(const float2* __restrict__ Hin,
                                           float* __restrict__ Hout,
                                           const float* __restrict__ Wg,
                                           const float* __restrict__ bg,
                                           int n, int outc, int relu) {
    __shared__ float Ws[64 * 64];
    __shared__ float bs[64];
    int tid = threadIdx.x;
    for (int i = tid; i < 64 * 64; i += 256) Ws[i] = 0.f;
    __syncthreads();
    for (int i = tid; i < 64 * outc; i += 256) {
        int k = i / outc, c = i % outc;
        Ws[k * 64 + c] = Wg[i];
    }
    if (tid < 64) bs[tid] = (tid < outc) ? bg[tid] : 0.f;
    __syncthreads();

    int warp = tid >> 5;
    int lane = tid & 31;
    int c0 = lane * 2;

    for (int node = blockIdx.x * 8 + warp; node < n; node += gridDim.x * 8) {
        int beg = g_offs[node];
        int end = g_offs[node + 1];
        float2 acc = make_float2(0.f, 0.f);
        int e = beg;
        // unroll-4: perm loads issued first, then all 4 gathers (MLP=4)
        for (; e + 4 <= end; e += 4) {
            uint2 p0 = g_perm[e + 0];
            uint2 p1 = g_perm[e + 1];
            uint2 p2 = g_perm[e + 2];
            uint2 p3 = g_perm[e + 3];
            float2 v0 = Hin[p0.x * 32u + lane];
            float2 v1 = Hin[p1.x * 32u + lane];
            float2 v2 = Hin[p2.x * 32u + lane];
            float2 v3 = Hin[p3.x * 32u + lane];
            float w0 = __uint_as_float(p0.y);
            float w1 = __uint_as_float(p1.y);
            float w2 = __uint_as_float(p2.y);
            float w3 = __uint_as_float(p3.y);
            acc.x = fmaf(w0, v0.x, acc.x); acc.y = fmaf(w0, v0.y, acc.y);
            acc.x = fmaf(w1, v1.x, acc.x); acc.y = fmaf(w1, v1.y, acc.y);
            acc.x = fmaf(w2, v2.x, acc.x); acc.y = fmaf(w2, v2.y, acc.y);
            acc.x = fmaf(w3, v3.x, acc.x); acc.y = fmaf(w3, v3.y, acc.y);
        }
        for (; e < end; ++e) {
            uint2 p = g_perm[e];
            float2 v = Hin[p.x * 32u + lane];
            float w = __uint_as_float(p.y);
            acc.x = fmaf(w, v.x, acc.x);
            acc.y = fmaf(w, v.y, acc.y);
        }

        // mini-GEMM: out[c0,c0+1] = sum_k row[k] * Ws[k][c0..c0+1] + b
        // row[2j]=acc.x@lane j, row[2j+1]=acc.y@lane j (shuffle broadcast)
        float ox = bs[c0];
        float oy = bs[c0 + 1];
#pragma unroll
        for (int k2 = 0; k2 < 32; k2++) {
            float rx = __shfl_sync(0xffffffffu, acc.x, k2);
            float ry = __shfl_sync(0xffffffffu, acc.y, k2);
            float2 w0 = *(const float2*)&Ws[(2 * k2) * 64 + c0];
            float2 w1 = *(const float2*)&Ws[(2 * k2 + 1) * 64 + c0];
            ox = fmaf(rx, w0.x, ox); oy = fmaf(rx, w0.y, oy);
            ox = fmaf(ry, w1.x, ox); oy = fmaf(ry, w1.y, oy);
        }
        if (relu) { ox = fmaxf(ox, 0.f); oy = fmaxf(oy, 0.f); }

        if (outc == 64) {
            ((float2*)Hout)[node * 32 + lane] = make_float2(ox, oy);
        } else {
            if (c0 + 1 < outc)
                *(float2*)(Hout + (size_t)node * outc + c0) = make_float2(ox, oy);
            else if (c0 < outc)
                Hout[(size_t)node * outc + c0] = ox;
        }
    }
}

// Variants (device globals referenced directly; no cudaGetSymbolAddress)
__global__ void __launch_bounds__(256, 6)
k_layer0(const float2* __restrict__ x, const float* __restrict__ Wg,
         const float* __restrict__ bg, int n) {
    layer_body(x, g_bufA, Wg, bg, n, 64, 1);
}
__global__ void __launch_bounds__(256, 6)
k_layer_AB(const float* __restrict__ Wg, const float* __restrict__ bg, int n) {
    layer_body((const float2*)g_bufA, g_bufB, Wg, bg, n, 64, 1);
}
__global__ void __launch_bounds__(256, 6)
k_layer_BA(const float* __restrict__ Wg, const float* __restrict__ bg, int n) {
    layer_body((const float2*)g_bufB, g_bufA, Wg, bg, n, 64, 1);
}
__global__ void __launch_bounds__(256, 6)
k_layer_Bout(const float* __restrict__ Wg, const float* __restrict__ bg,
             float* __restrict__ out, int n, int outc) {
    layer_body((const float2*)g_bufB, out, Wg, bg, n, outc, 0);
}

// ---------------------------------------------------------------------------
// Launch
// inputs: x[N,64], edge_weight[E], W[4,64,64], b[4,64], W_out[64,40],
//         b_out[40], edge_src[E], edge_dst[E]  -> out[N,40] f32
// ---------------------------------------------------------------------------
extern "C" void kernel_launch(void* const* d_in, const int* in_sizes, int n_in,
                              void* d_out, int out_size) {
    const float* x    = (const float*)d_in[0];
    const float* ew   = (const float*)d_in[1];
    const float* W    = (const float*)d_in[2];
    const float* b    = (const float*)d_in[3];
    const float* Wout = (const float*)d_in[4];
    const float* bout = (const float*)d_in[5];
    const int*   esrc = (const int*)d_in[6];
    const int*   edst = (const int*)d_in[7];

    int n = in_sizes[0] / 64;   // 100000
    int e = in_sizes[6];        // 1600000

    // --- CSR build (dst-sorted) ---
    k_zero_offs<<<(n + 256) / 256, 256>>>(n + 1);
    k_hist<<<(e + 255) / 256, 256>>>(edst, e);
    k_scan<<<1, 1024>>>(n + 1, n);
    k_scatter<<<(e + 255) / 256, 256>>>(esrc, edst, ew, e);

    // --- 5 fused layers (ping-pong A/B) ---
    k_layer0   <<<LAYER_BLOCKS, 256>>>((const float2*)x, W, b, n);
    k_layer_AB <<<LAYER_BLOCKS, 256>>>(W + 1 * 64 * 64, b + 1 * 64, n);
    k_layer_BA <<<LAYER_BLOCKS, 256>>>(W + 2 * 64 * 64, b + 2 * 64, n);
    k_layer_AB <<<LAYER_BLOCKS, 256>>>(W + 3 * 64 * 64, b + 3 * 64, n);
    k_layer_Bout<<<LAYER_BLOCKS, 256>>>(Wout, bout, (float*)d_out, n, 40);
}